// round 5
// baseline (speedup 1.0000x reference)
#include <cuda_runtime.h>
#include <math.h>

#define Bsz 64
#define Tn  256
#define Dn  256
#define Hn  256
#define Cn  32
#define G4  1024              // 4*H
#define Mrows (Bsz*Tn)        // 16384

// ---------------- static device scratch (no allocations allowed) -------------
__device__ float d_X   [Mrows*Dn];      // embedded inputs            (16.8 MB)
__device__ float d_Xrev[Mrows*Dn];      // per-length reversed inputs (16.8 MB)
__device__ float d_G   [2][Mrows*G4];   // precomputed x@W_ih^T + b   (134 MB)
__device__ float d_Hf  [Bsz*Tn*Hn];     // forward  LSTM outputs
__device__ float d_Hb  [Bsz*Tn*Hn];     // backward LSTM outputs (raw reversed order)
__device__ float d_cst [2*Bsz*Hn];      // cell state
__device__ float d_em  [Bsz*Tn*Cn];     // emissions

__device__ __forceinline__ float sigf(float x) { return 1.0f / (1.0f + expf(-x)); }

// ---------------- 1) embedding gather (+ reversed copy) ----------------------
__global__ void gather_kernel(const int* __restrict__ sent,
                              const int* __restrict__ lens,
                              const float* __restrict__ emb)
{
    int bt = blockIdx.x;
    int b = bt >> 8, t = bt & 255;
    int len = lens[b];
    int tr = (t < len) ? (len - 1 - t) : t;
    int tok  = sent[bt];
    int tokr = sent[b * Tn + tr];
    int k = threadIdx.x;
    d_X   [(size_t)bt * Dn + k] = emb[(size_t)tok  * Dn + k];
    d_Xrev[(size_t)bt * Dn + k] = emb[(size_t)tokr * Dn + k];
}

// ---------------- 2) input projection GEMM: G = X @ W_ih^T + (b_ih+b_hh) -----
// C[M=16384, N=1024] = A[M,256] * W[N,256]^T ; 128x128 block tile, BK=8, 8x8/thread
__global__ void input_gemm_kernel(const float* __restrict__ wf, const float* __restrict__ bif,
                                  const float* __restrict__ bhf,
                                  const float* __restrict__ wb, const float* __restrict__ bib,
                                  const float* __restrict__ bhb)
{
    __shared__ float As[8][132];
    __shared__ float Bs[8][132];

    int dir = blockIdx.z;
    const float* A  = dir ? d_Xrev : d_X;
    const float* W  = dir ? wb  : wf;
    const float* bi = dir ? bib : bif;
    const float* bh = dir ? bhb : bhf;
    float* Cc = d_G[dir];

    int tid = threadIdx.x;              // 256 threads
    int m0 = blockIdx.y << 7;
    int n0 = blockIdx.x << 7;
    int tx = tid & 15, ty = tid >> 4;

    int lrow = tid >> 1;
    int lcol = (tid & 1) << 2;

    float acc[8][8];
#pragma unroll
    for (int i = 0; i < 8; i++)
#pragma unroll
        for (int j = 0; j < 8; j++) acc[i][j] = 0.0f;

    const float* Aptr = A + (size_t)(m0 + lrow) * Dn + lcol;
    const float* Wptr = W + (size_t)(n0 + lrow) * Dn + lcol;

    for (int k0 = 0; k0 < Dn; k0 += 8) {
        float4 av = *(const float4*)(Aptr + k0);
        float4 bv = *(const float4*)(Wptr + k0);
        As[lcol + 0][lrow] = av.x; As[lcol + 1][lrow] = av.y;
        As[lcol + 2][lrow] = av.z; As[lcol + 3][lrow] = av.w;
        Bs[lcol + 0][lrow] = bv.x; Bs[lcol + 1][lrow] = bv.y;
        Bs[lcol + 2][lrow] = bv.z; Bs[lcol + 3][lrow] = bv.w;
        __syncthreads();
#pragma unroll
        for (int kk = 0; kk < 8; kk++) {
            float ar[8], br[8];
#pragma unroll
            for (int i = 0; i < 8; i++) ar[i] = As[kk][(ty << 3) + i];
#pragma unroll
            for (int j = 0; j < 8; j++) br[j] = Bs[kk][(tx << 3) + j];
#pragma unroll
            for (int i = 0; i < 8; i++)
#pragma unroll
                for (int j = 0; j < 8; j++) acc[i][j] += ar[i] * br[j];
        }
        __syncthreads();
    }

#pragma unroll
    for (int i = 0; i < 8; i++) {
        size_t row = (size_t)m0 + (ty << 3) + i;
#pragma unroll
        for (int j = 0; j < 8; j += 4) {
            int col = n0 + (tx << 3) + j;
            float4 v;
            v.x = acc[i][j]     + bi[col]     + bh[col];
            v.y = acc[i][j + 1] + bi[col + 1] + bh[col + 1];
            v.z = acc[i][j + 2] + bi[col + 2] + bh[col + 2];
            v.w = acc[i][j + 3] + bi[col + 3] + bh[col + 3];
            *(float4*)(Cc + row * G4 + col) = v;
        }
    }
}

// ---------------- 3) one LSTM timestep (both directions) ---------------------
// grid (64 chunks, 2 dirs), 256 threads. Chunk owns 4 hidden units -> 16 gate rows.
// gates[b, row] = G[dir,b,t,row] + sum_k h_prev[b,k] * W_hh[row,k]
__global__ void lstm_step_kernel(int t, const float* __restrict__ whh_f,
                                 const float* __restrict__ whh_b)
{
    __shared__ float w_sh[16][260];
    __shared__ float h_sh[64][68];
    __shared__ float gate_sh[64][17];

    int dir = blockIdx.y;
    int chunk = blockIdx.x;
    int k0 = chunk << 2;
    int tid = threadIdx.x;
    const float* W = dir ? whh_b : whh_f;       // [1024, 256]
    float* Hist = dir ? d_Hb : d_Hf;            // [B][T][H]
    const float* Gp = d_G[dir];                 // [B*T][1024]

    // cache the 16 W_hh rows this block owns
    for (int i = tid; i < 16 * 64; i += 256) {
        int r  = i >> 6;
        int c4 = (i & 63) << 2;
        int grow = ((r >> 2) << 8) + k0 + (r & 3);   // q*256 + k0 + j
        float4 v = *(const float4*)(W + (size_t)grow * Hn + c4);
        w_sh[r][c4] = v.x; w_sh[r][c4 + 1] = v.y; w_sh[r][c4 + 2] = v.z; w_sh[r][c4 + 3] = v.w;
    }

    int r2 = tid & 7, b2 = tid >> 3;
    int r0 = r2 << 1, b0 = b2 << 1;
    float acc00 = 0.f, acc01 = 0.f, acc10 = 0.f, acc11 = 0.f;

    if (t > 0) {
        for (int kt = 0; kt < 4; kt++) {
            __syncthreads();
            for (int i = tid; i < 1024; i += 256) {
                int bb = i >> 4;
                int c4 = (i & 15) << 2;
                float4 v = *(const float4*)(Hist + (size_t)bb * Tn * Hn +
                                            (size_t)(t - 1) * Hn + (kt << 6) + c4);
                h_sh[bb][c4] = v.x; h_sh[bb][c4 + 1] = v.y;
                h_sh[bb][c4 + 2] = v.z; h_sh[bb][c4 + 3] = v.w;
            }
            __syncthreads();
#pragma unroll
            for (int kk = 0; kk < 64; kk += 4) {
                float4 h0 = *(const float4*)&h_sh[b0][kk];
                float4 h1 = *(const float4*)&h_sh[b0 + 1][kk];
                float4 w0 = *(const float4*)&w_sh[r0][(kt << 6) + kk];
                float4 w1 = *(const float4*)&w_sh[r0 + 1][(kt << 6) + kk];
                acc00 += h0.x * w0.x + h0.y * w0.y + h0.z * w0.z + h0.w * w0.w;
                acc01 += h0.x * w1.x + h0.y * w1.y + h0.z * w1.z + h0.w * w1.w;
                acc10 += h1.x * w0.x + h1.y * w0.y + h1.z * w0.z + h1.w * w0.w;
                acc11 += h1.x * w1.x + h1.y * w1.y + h1.z * w1.z + h1.w * w1.w;
            }
        }
    }

    // stage gates (+ precomputed input part)
    {
        float a[2][2] = {{acc00, acc01}, {acc10, acc11}};
#pragma unroll
        for (int bi = 0; bi < 2; bi++)
#pragma unroll
            for (int ri = 0; ri < 2; ri++) {
                int lr = r0 + ri;
                int grow = ((lr >> 2) << 8) + k0 + (lr & 3);
                float g = Gp[((size_t)(b0 + bi) * Tn + t) * G4 + grow] + a[bi][ri];
                gate_sh[b0 + bi][lr] = g;
            }
    }
    __syncthreads();

    // elementwise LSTM update: 256 threads = 64 batch x 4 hidden units
    {
        int b = tid >> 2, j = tid & 3;
        float gi = gate_sh[b][j];
        float gf = gate_sh[b][4 + j];
        float gg = gate_sh[b][8 + j];
        float go = gate_sh[b][12 + j];
        int ci = (dir * Bsz + b) * Hn + k0 + j;
        float cprev = (t > 0) ? d_cst[ci] : 0.0f;
        float cc = sigf(gf) * cprev + sigf(gi) * tanhf(gg);
        float hh = sigf(go) * tanhf(cc);
        d_cst[ci] = cc;
        Hist[(size_t)b * Tn * Hn + (size_t)t * Hn + k0 + j] = hh;
    }
}

// ---------------- 4) emissions: e = [Hf, Hb(un-reversed)] @ w_out^T + b_out --
// 256 blocks x 256 threads; each block: 64 (b,t) rows x 32 tags, K tiled by 64
__global__ void emissions_kernel(const float* __restrict__ w_out,
                                 const float* __restrict__ b_out,
                                 const int* __restrict__ lens)
{
    __shared__ float A_sh[64][68];
    __shared__ float w_sh[32][68];

    int blk = blockIdx.x;
    int bt0 = blk << 6;
    int b = bt0 >> 8;                 // 4 blocks per batch element
    int tid = threadIdx.x;
    int len = lens[b];

    int c = tid & 31, rg = tid >> 5;
    float acc[8];
#pragma unroll
    for (int i = 0; i < 8; i++) acc[i] = 0.0f;

    for (int kt = 0; kt < 8; kt++) {
        __syncthreads();
        for (int i = tid; i < 1024; i += 256) {
            int r  = i >> 4;
            int c4 = (i & 15) << 2;
            int t = (bt0 + r) & 255;
            const float* src;
            if (kt < 4) {
                src = d_Hf + (size_t)b * Tn * Hn + (size_t)t * Hn + (kt << 6) + c4;
            } else {
                int trr = (t < len) ? (len - 1 - t) : t;
                src = d_Hb + (size_t)b * Tn * Hn + (size_t)trr * Hn + ((kt - 4) << 6) + c4;
            }
            float4 v = *(const float4*)src;
            A_sh[r][c4] = v.x; A_sh[r][c4 + 1] = v.y; A_sh[r][c4 + 2] = v.z; A_sh[r][c4 + 3] = v.w;
        }
        for (int i = tid; i < 512; i += 256) {
            int r = i >> 4, c4 = (i & 15) << 2;
            float4 v = *(const float4*)(w_out + (size_t)r * 512 + (kt << 6) + c4);
            w_sh[r][c4] = v.x; w_sh[r][c4 + 1] = v.y; w_sh[r][c4 + 2] = v.z; w_sh[r][c4 + 3] = v.w;
        }
        __syncthreads();
#pragma unroll 8
        for (int kk = 0; kk < 64; kk++) {
            float w = w_sh[c][kk];
#pragma unroll
            for (int i = 0; i < 8; i++) acc[i] += A_sh[(rg << 3) + i][kk] * w;
        }
    }

    float bb = b_out[c];
#pragma unroll
    for (int i = 0; i < 8; i++) {
        int bt = bt0 + (rg << 3) + i;
        d_em[(size_t)bt * Cn + c] = acc[i] + bb;
    }
}

// ---------------- 5) Viterbi decode: 64 blocks (one per batch), 32 threads ---
__global__ void viterbi_kernel(const float* __restrict__ st, const float* __restrict__ et,
                               const float* __restrict__ tr, const int* __restrict__ lens,
                               float* __restrict__ out)
{
    __shared__ float trans_sh[1024];
    __shared__ float score[32];
    __shared__ unsigned char bp[256][32];

    int b = blockIdx.x;
    int c = threadIdx.x;
    for (int i = c; i < 1024; i += 32) trans_sh[i] = tr[i];
    int len = lens[b];

    score[c] = st[c] + d_em[(size_t)(b * Tn) * Cn + c];
    __syncwarp();

    for (int t = 1; t < Tn; t++) {
        float em = d_em[(size_t)(b * Tn + t) * Cn + c];
        float best = score[0] + trans_sh[c];
        int bpi = 0;
#pragma unroll
        for (int p = 1; p < 32; p++) {
            float v = score[p] + trans_sh[(p << 5) + c];
            if (v > best) { best = v; bpi = p; }   // first-max like jnp.argmax
        }
        float ns = (t < len) ? (best + em) : score[c];
        __syncwarp();
        score[c] = ns;
        bp[t][c] = (unsigned char)bpi;
        __syncwarp();
    }

    float fin = score[c] + et[c];
    __syncwarp();
    score[c] = fin;
    __syncwarp();

    if (c == 0) {
        float bs = score[0]; int bl = 0;
        for (int p = 1; p < 32; p++)
            if (score[p] > bs) { bs = score[p]; bl = p; }
        out[Bsz * Tn + b] = bs;                 // best_score after all paths
        int tag = bl;
        out[b * Tn + (Tn - 1)] = (float)tag;
        for (int t = Tn - 2; t >= 0; t--) {
            if (t < len - 1) tag = bp[t + 1][tag];
            out[b * Tn + t] = (float)tag;
        }
    }
}

// ---------------------------------- launch -----------------------------------
extern "C" void kernel_launch(void* const* d_in, const int* in_sizes, int n_in,
                              void* d_out, int out_size)
{
    const int*   sent   = (const int*)d_in[0];
    const int*   lens   = (const int*)d_in[1];
    const float* emb    = (const float*)d_in[2];
    const float* w_ih_f = (const float*)d_in[3];
    const float* w_hh_f = (const float*)d_in[4];
    const float* b_ih_f = (const float*)d_in[5];
    const float* b_hh_f = (const float*)d_in[6];
    const float* w_ih_b = (const float*)d_in[7];
    const float* w_hh_b = (const float*)d_in[8];
    const float* b_ih_b = (const float*)d_in[9];
    const float* b_hh_b = (const float*)d_in[10];
    const float* w_out  = (const float*)d_in[11];
    const float* b_out  = (const float*)d_in[12];
    const float* st     = (const float*)d_in[13];
    const float* et     = (const float*)d_in[14];
    const float* tr     = (const float*)d_in[15];
    float* out = (float*)d_out;

    gather_kernel<<<Mrows, 256>>>(sent, lens, emb);

    dim3 ggrid(G4 / 128, Mrows / 128, 2);
    input_gemm_kernel<<<ggrid, 256>>>(w_ih_f, b_ih_f, b_hh_f,
                                      w_ih_b, b_ih_b, b_hh_b);

    for (int t = 0; t < Tn; t++)
        lstm_step_kernel<<<dim3(64, 2), 256>>>(t, w_hh_f, w_hh_b);

    emissions_kernel<<<Mrows / 64, 256>>>(w_out, b_out, lens);

    viterbi_kernel<<<Bsz, 32>>>(st, et, tr, lens, out);
}